// round 5
// baseline (speedup 1.0000x reference)
#include <cuda_runtime.h>
#include <cuda_bf16.h>
#include <stdint.h>

#define NN 100000
#define NE 600000
#define HD 128
#define NL 6
#define NG 1024
#define NTILES ((NN + 127) / 128)   // 782
#define SCAN_BLOCKS 98              // ceil(100000/1024)
#define PAD 136                     // bf16 elements per smem row (272B, 16B-aligned, conflict-free)

// ---------------- device scratch (no dynamic allocation allowed) ----------------
__device__ float g_h[NN * HD];            // hidden state between layers
__device__ float g_z[NN * HD];            // aggregated input to MLP
__device__ int g_cnt[NN];
__device__ int g_cur[NN];
__device__ int g_off[NN + 1];
__device__ int g_srclist[NE];
__device__ int g_bsum[SCAN_BLOCKS];
// per layer: [W1hi, W1lo, W2hi, W2lo], each [n][k] (transposed for row.col mma B operand)
__device__ __align__(16) __nv_bfloat16 g_wsplit[NL][4][HD * HD];

// ---------------- mma.sync bf16 (sm_80+ ISA, assembles at sm_100) ----------------
__device__ __forceinline__ void mma_bf16(float* d, const uint32_t* a, const uint32_t* b) {
    asm volatile(
        "mma.sync.aligned.m16n8k16.row.col.f32.bf16.bf16.f32 "
        "{%0,%1,%2,%3}, {%4,%5,%6,%7}, {%8,%9}, {%0,%1,%2,%3};\n"
        : "+f"(d[0]), "+f"(d[1]), "+f"(d[2]), "+f"(d[3])
        : "r"(a[0]), "r"(a[1]), "r"(a[2]), "r"(a[3]), "r"(b[0]), "r"(b[1]));
}

// ---------------- weight prep: transpose + bf16 hi/lo split ----------------
__global__ void k_prep_weights(const float* __restrict__ W1, const float* __restrict__ W2) {
    int idx = blockIdx.x * blockDim.x + threadIdx.x;
    if (idx >= NL * HD * HD) return;
    int l = idx / (HD * HD);
    int rem = idx % (HD * HD);
    int k = rem / HD;   // input-feature index (row of W)
    int n = rem % HD;   // output-feature index (col of W)
#pragma unroll
    for (int m = 0; m < 2; m++) {
        float w = (m ? W2 : W1)[idx];
        __nv_bfloat16 hi = __float2bfloat16(w);
        __nv_bfloat16 lo = __float2bfloat16(w - __bfloat162float(hi));
        g_wsplit[l][m * 2][n * HD + k] = hi;      // B stored [n][k] for row.col mma
        g_wsplit[l][m * 2 + 1][n * HD + k] = lo;
    }
}

// ---------------- CSR build (by dst) ----------------
__global__ void k_zero() {
    int i = blockIdx.x * blockDim.x + threadIdx.x;
    if (i < NN) { g_cnt[i] = 0; g_cur[i] = 0; }
}
__global__ void k_count(const int* __restrict__ edge) {
    int e = blockIdx.x * blockDim.x + threadIdx.x;
    if (e < NE) atomicAdd(&g_cnt[edge[NE + e]], 1);
}
__global__ void k_scan1() {
    __shared__ int s[1024];
    int t = threadIdx.x;
    int i = blockIdx.x * 1024 + t;
    int v = (i < NN) ? g_cnt[i] : 0;
    s[t] = v;
    __syncthreads();
    for (int d = 1; d < 1024; d <<= 1) {
        int x = (t >= d) ? s[t - d] : 0;
        __syncthreads();
        s[t] += x;
        __syncthreads();
    }
    if (i <= NN) g_off[i] = s[t] - v;
    if (t == 1023) g_bsum[blockIdx.x] = s[1023];
}
__global__ void k_scan2() {
    if (threadIdx.x == 0) {
        int acc = 0;
        for (int i = 0; i < SCAN_BLOCKS; i++) { int v = g_bsum[i]; g_bsum[i] = acc; acc += v; }
    }
}
__global__ void k_scan3() {
    int i = blockIdx.x * 1024 + threadIdx.x;
    if (i <= NN) g_off[i] += g_bsum[blockIdx.x];
}
__global__ void k_fill(const int* __restrict__ edge) {
    int e = blockIdx.x * blockDim.x + threadIdx.x;
    if (e < NE) {
        int d = edge[NE + e];
        int p = atomicAdd(&g_cur[d], 1);
        g_srclist[g_off[d] + p] = edge[e];
    }
}

// ---------------- gather: z[i] = h[i] + sum_{j->i} h[j] (warp per node) ----------------
__global__ void k_gather(const float* __restrict__ xin, int first) {
    const float* h = first ? xin : (const float*)g_h;
    int w = (blockIdx.x * blockDim.x + threadIdx.x) >> 5;
    int lane = threadIdx.x & 31;
    if (w >= NN) return;
    int beg = g_off[w], end = g_off[w + 1];
    const float4* hv = (const float4*)h;
    float4 acc = hv[(size_t)w * 32 + lane];
    for (int e = beg; e < end; e++) {
        int s = g_srclist[e];
        float4 v = __ldg(&hv[(size_t)s * 32 + lane]);
        acc.x += v.x; acc.y += v.y; acc.z += v.z; acc.w += v.w;
    }
    ((float4*)g_z)[(size_t)w * 32 + lane] = acc;
}

// ---------------- fused 2-layer MLP via mma.sync bf16x3 ----------------
// smem: Ahi[128][PAD], Alo[128][PAD], W[4][128][PAD]  (all bf16)
#define SM_TOTAL (6 * 128 * PAD * 2)   // 208,896 bytes

__device__ __forceinline__ void gemm_tile(
    const __nv_bfloat16* __restrict__ Ahi, const __nv_bfloat16* __restrict__ Alo,
    const __nv_bfloat16* __restrict__ Bhi, const __nv_bfloat16* __restrict__ Blo,
    float acc[2][8][4], int wr, int wc, int lane)
{
    int ar = wr * 32 + (lane >> 2);
    int bn = wc * 64 + (lane >> 2);
    int kk = (lane & 3) * 2;
#pragma unroll
    for (int term = 0; term < 3; term++) {
        const __nv_bfloat16* Ap = (term == 2) ? Alo : Ahi;
        const __nv_bfloat16* Bp = (term == 1) ? Blo : Bhi;
#pragma unroll
        for (int ks = 0; ks < 8; ks++) {
            int k0 = ks * 16 + kk;
            uint32_t a[2][4], b[8][2];
#pragma unroll
            for (int mt = 0; mt < 2; mt++) {
                const __nv_bfloat16* base = Ap + (ar + mt * 16) * PAD + k0;
                a[mt][0] = *(const uint32_t*)(base);
                a[mt][1] = *(const uint32_t*)(base + 8 * PAD);
                a[mt][2] = *(const uint32_t*)(base + 8);
                a[mt][3] = *(const uint32_t*)(base + 8 * PAD + 8);
            }
#pragma unroll
            for (int nt = 0; nt < 8; nt++) {
                const __nv_bfloat16* base = Bp + (bn + nt * 8) * PAD + k0;
                b[nt][0] = *(const uint32_t*)(base);
                b[nt][1] = *(const uint32_t*)(base + 8);
            }
#pragma unroll
            for (int mt = 0; mt < 2; mt++)
#pragma unroll
                for (int nt = 0; nt < 8; nt++)
                    mma_bf16(acc[mt][nt], a[mt], b[nt]);
        }
    }
}

__global__ void __launch_bounds__(256, 1) k_mlp(
    int layer, const float* __restrict__ b1, const float* __restrict__ b2,
    int last, float* __restrict__ xoutp)
{
    extern __shared__ __nv_bfloat16 sm[];
    __nv_bfloat16* Ahi = sm;
    __nv_bfloat16* Alo = sm + 128 * PAD;
    __nv_bfloat16* Wb  = sm + 2 * 128 * PAD;   // [4 mats][128 rows][PAD]
    float* outp = last ? xoutp : (float*)g_h;

    int tid = threadIdx.x, lane = tid & 31, warp = tid >> 5;
    int wr = warp >> 1, wc = warp & 1;   // warp tile: rows wr*32..+31, cols wc*64..+63

    // stage this layer's 4 weight images (coalesced, add padding on the fly)
    {
        const uint4* src = (const uint4*)&g_wsplit[layer][0][0];
        for (int i = tid; i < 4 * 128 * 16; i += 256) {
            int matrow = i >> 4;   // 0..511
            int q = i & 15;
            ((uint4*)&Wb[matrow * PAD])[q] = src[i];
        }
    }

    // per-thread bias registers (columns this thread owns)
    float bv1[16], bv2[16];
    int cb = wc * 64 + (lane & 3) * 2;
#pragma unroll
    for (int nt = 0; nt < 8; nt++) {
        bv1[nt * 2]     = __ldg(&b1[cb + nt * 8]);
        bv1[nt * 2 + 1] = __ldg(&b1[cb + nt * 8 + 1]);
        bv2[nt * 2]     = __ldg(&b2[cb + nt * 8]);
        bv2[nt * 2 + 1] = __ldg(&b2[cb + nt * 8 + 1]);
    }
    __syncthreads();

    const __nv_bfloat16* W1hi = Wb;
    const __nv_bfloat16* W1lo = Wb + 128 * PAD;
    const __nv_bfloat16* W2hi = Wb + 2 * 128 * PAD;
    const __nv_bfloat16* W2lo = Wb + 3 * 128 * PAD;

    for (int tile = blockIdx.x; tile < NTILES; tile += gridDim.x) {
        int row0 = tile * 128;

        // ---- load A tile from g_z, split to bf16 hi/lo (64-bit conflict-free stores) ----
        for (int i = tid; i < 128 * 32; i += 256) {
            int r = i >> 5, c4 = i & 31;
            float4 v = make_float4(0.f, 0.f, 0.f, 0.f);
            if (row0 + r < NN) v = ((const float4*)g_z)[(size_t)(row0 + r) * 32 + c4];
            __nv_bfloat16 h0 = __float2bfloat16(v.x), h1 = __float2bfloat16(v.y);
            __nv_bfloat16 h2 = __float2bfloat16(v.z), h3 = __float2bfloat16(v.w);
            __nv_bfloat162 hp0 = __halves2bfloat162(h0, h1);
            __nv_bfloat162 hp1 = __halves2bfloat162(h2, h3);
            __nv_bfloat162 lp0 = __floats2bfloat162_rn(v.x - __bfloat162float(h0), v.y - __bfloat162float(h1));
            __nv_bfloat162 lp1 = __floats2bfloat162_rn(v.z - __bfloat162float(h2), v.w - __bfloat162float(h3));
            uint2 hv2 = make_uint2(*(uint32_t*)&hp0, *(uint32_t*)&hp1);
            uint2 lv2 = make_uint2(*(uint32_t*)&lp0, *(uint32_t*)&lp1);
            *(uint2*)&Ahi[r * PAD + c4 * 4] = hv2;
            *(uint2*)&Alo[r * PAD + c4 * 4] = lv2;
        }
        __syncthreads();

        // ---- GEMM1: acc = A @ W1 (bf16x3) ----
        float acc[2][8][4];
#pragma unroll
        for (int mt = 0; mt < 2; mt++)
#pragma unroll
            for (int nt = 0; nt < 8; nt++)
#pragma unroll
                for (int j = 0; j < 4; j++) acc[mt][nt][j] = 0.f;
        gemm_tile(Ahi, Alo, W1hi, W1lo, acc, wr, wc, lane);
        __syncthreads();   // all GEMM1 reads of A done before overwrite

        // ---- epilogue1: z1 = relu(acc + b1), re-split into Ahi/Alo ----
#pragma unroll
        for (int mt = 0; mt < 2; mt++) {
            int r0 = wr * 32 + mt * 16 + (lane >> 2);
            int r1 = r0 + 8;
#pragma unroll
            for (int nt = 0; nt < 8; nt++) {
                int c = wc * 64 + nt * 8 + (lane & 3) * 2;
                float v0 = fmaxf(acc[mt][nt][0] + bv1[nt * 2],     0.f);
                float v1 = fmaxf(acc[mt][nt][1] + bv1[nt * 2 + 1], 0.f);
                float v2 = fmaxf(acc[mt][nt][2] + bv1[nt * 2],     0.f);
                float v3 = fmaxf(acc[mt][nt][3] + bv1[nt * 2 + 1], 0.f);
                __nv_bfloat16 h0 = __float2bfloat16(v0), h1 = __float2bfloat16(v1);
                __nv_bfloat16 h2 = __float2bfloat16(v2), h3 = __float2bfloat16(v3);
                __nv_bfloat162 hp0 = __halves2bfloat162(h0, h1);
                __nv_bfloat162 hp1 = __halves2bfloat162(h2, h3);
                __nv_bfloat162 lp0 = __floats2bfloat162_rn(v0 - __bfloat162float(h0), v1 - __bfloat162float(h1));
                __nv_bfloat162 lp1 = __floats2bfloat162_rn(v2 - __bfloat162float(h2), v3 - __bfloat162float(h3));
                *(uint32_t*)&Ahi[r0 * PAD + c] = *(uint32_t*)&hp0;
                *(uint32_t*)&Alo[r0 * PAD + c] = *(uint32_t*)&lp0;
                *(uint32_t*)&Ahi[r1 * PAD + c] = *(uint32_t*)&hp1;
                *(uint32_t*)&Alo[r1 * PAD + c] = *(uint32_t*)&lp1;
            }
        }
        __syncthreads();

        // ---- GEMM2: acc = z1 @ W2 ----
#pragma unroll
        for (int mt = 0; mt < 2; mt++)
#pragma unroll
            for (int nt = 0; nt < 8; nt++)
#pragma unroll
                for (int j = 0; j < 4; j++) acc[mt][nt][j] = 0.f;
        gemm_tile(Ahi, Alo, W2hi, W2lo, acc, wr, wc, lane);
        __syncthreads();   // all GEMM2 reads done before next tile's A overwrite

        // ---- epilogue2: h = relu(acc + b2) -> global fp32 ----
#pragma unroll
        for (int mt = 0; mt < 2; mt++) {
            int r0 = row0 + wr * 32 + mt * 16 + (lane >> 2);
            int r1 = r0 + 8;
#pragma unroll
            for (int nt = 0; nt < 8; nt++) {
                int c = wc * 64 + nt * 8 + (lane & 3) * 2;
                if (r0 < NN) {
                    float2 v;
                    v.x = fmaxf(acc[mt][nt][0] + bv2[nt * 2],     0.f);
                    v.y = fmaxf(acc[mt][nt][1] + bv2[nt * 2 + 1], 0.f);
                    ((float2*)outp)[(size_t)r0 * 64 + (c >> 1)] = v;
                }
                if (r1 < NN) {
                    float2 v;
                    v.x = fmaxf(acc[mt][nt][2] + bv2[nt * 2],     0.f);
                    v.y = fmaxf(acc[mt][nt][3] + bv2[nt * 2 + 1], 0.f);
                    ((float2*)outp)[(size_t)r1 * 64 + (c >> 1)] = v;
                }
            }
        }
    }
}

// ---------------- mean pool per graph (batch is sorted) ----------------
__global__ void k_pool(const float* __restrict__ xout, const int* __restrict__ batch,
                       float* __restrict__ gout) {
    int b = blockIdx.x, t = threadIdx.x;
    int lo = 0, hi = NN;
    while (lo < hi) { int m = (lo + hi) >> 1; if (batch[m] < b) lo = m + 1; else hi = m; }
    int beg = lo;
    hi = NN;
    while (lo < hi) { int m = (lo + hi) >> 1; if (batch[m] <= b) lo = m + 1; else hi = m; }
    int end = lo;
    float acc = 0.f;
    for (int i = beg; i < end; i++) acc += xout[(size_t)i * HD + t];
    int cnt = end - beg;
    gout[b * HD + t] = acc / (float)(cnt > 0 ? cnt : 1);
}

// ---------------- launch ----------------
extern "C" void kernel_launch(void* const* d_in, const int* in_sizes, int n_in,
                              void* d_out, int out_size)
{
    const float* x   = (const float*)d_in[0];
    const int* edge  = (const int*)d_in[1];
    const int* batch = (const int*)d_in[2];
    const float* W1  = (const float*)d_in[3];
    const float* b1  = (const float*)d_in[4];
    const float* W2  = (const float*)d_in[5];
    const float* b2  = (const float*)d_in[6];
    float* out  = (float*)d_out;
    float* xout = out;
    float* gout = out + (size_t)NN * HD;

    cudaFuncSetAttribute(k_mlp, cudaFuncAttributeMaxDynamicSharedMemorySize, SM_TOTAL);

    k_prep_weights<<<(NL * HD * HD + 255) / 256, 256>>>(W1, W2);
    k_zero<<<(NN + 255) / 256, 256>>>();
    k_count<<<(NE + 255) / 256, 256>>>(edge);
    k_scan1<<<SCAN_BLOCKS, 1024>>>();
    k_scan2<<<1, 32>>>();
    k_scan3<<<SCAN_BLOCKS, 1024>>>();
    k_fill<<<(NE + 255) / 256, 256>>>(edge);

    for (int l = 0; l < NL; l++) {
        k_gather<<<(NN * 32 + 255) / 256, 256>>>(x, l == 0 ? 1 : 0);
        k_mlp<<<148, 256, SM_TOTAL>>>(l, b1 + (size_t)l * HD, b2 + (size_t)l * HD,
                                      (l == NL - 1) ? 1 : 0, xout);
    }
    k_pool<<<NG, HD>>>(xout, batch, gout);
}